// round 8
// baseline (speedup 1.0000x reference)
#include <cuda_runtime.h>
#include <cuda_bf16.h>
#include <cstdint>

// Problem dims (fixed by the dataset)
#define L_DIM 131072
#define B_DIM 512
#define D_DIM 768
#define NNZ_DIM 2048

#define K3_SPLITS 32
#define K3_CHUNK (L_DIM / K3_SPLITS)   // 4096

// GEMM tiling (mma.sync path, plain sm_100-compatible)
#define CTA_M 128
#define CTA_N 128
#define CTA_K 32
#define STAGES 3
#define ROW_PITCH 80                     // 64B data + 16B pad -> conflict-free LDSM
#define BUF_BYTES (128 * ROW_PITCH)      // 10240 per operand-half
#define STAGE_BYTES (4 * BUF_BYTES)      // Ahi, Alo, Bhi, Blo = 40960
#define GEMM_SMEM (STAGES * STAGE_BYTES) // 122880

// ---------------------------------------------------------------------------
// Scratch (__device__ globals = allocation-free scratch)
// ---------------------------------------------------------------------------
static __device__ float          g_buf[(size_t)L_DIM * B_DIM];                 // fp32 g
static __device__ __nv_bfloat16  Whl [(size_t)2 * L_DIM * D_DIM];              // [2L, D]
static __device__ __nv_bfloat16  WThl[(size_t)2 * D_DIM * L_DIM];              // [2D, L]
static __device__ __nv_bfloat16  ghl [(size_t)2 * L_DIM * B_DIM];              // [2L, B]
static __device__ __nv_bfloat16  gThl[(size_t)2 * B_DIM * L_DIM];              // [2B, L]
static __device__ __nv_bfloat16  Ehl [(size_t)2 * B_DIM * D_DIM];              // [2B, D]
static __device__ __nv_bfloat16  EThl[(size_t)2 * D_DIM * B_DIM];              // [2D, B]
static __device__ float          part_buf[(size_t)K3_SPLITS * B_DIM * D_DIM];

// ---------------------------------------------------------------------------
// sm_80-level PTX helpers (legal on plain sm_100 target)
// ---------------------------------------------------------------------------
__device__ __forceinline__ uint32_t smem_u32(const void* p) {
    uint32_t a;
    asm("{ .reg .u64 t; cvta.to.shared.u64 t, %1; cvt.u32.u64 %0, t; }" : "=r"(a) : "l"(p));
    return a;
}
__device__ __forceinline__ void cp16(uint32_t dst, const void* src) {
    asm volatile("cp.async.cg.shared.global [%0], [%1], 16;" :: "r"(dst), "l"(src));
}
__device__ __forceinline__ void cp_commit() {
    asm volatile("cp.async.commit_group;" ::: "memory");
}
template <int N>
__device__ __forceinline__ void cp_wait() {
    asm volatile("cp.async.wait_group %0;" :: "n"(N) : "memory");
}
__device__ __forceinline__ void ldsm4(uint32_t* d, uint32_t addr) {
    asm volatile("ldmatrix.sync.aligned.m8n8.x4.shared.b16 {%0,%1,%2,%3}, [%4];"
        : "=r"(d[0]), "=r"(d[1]), "=r"(d[2]), "=r"(d[3]) : "r"(addr));
}
__device__ __forceinline__ void mma16816(float* c, const uint32_t* a, uint32_t b0, uint32_t b1) {
    asm volatile("mma.sync.aligned.m16n8k16.row.col.f32.bf16.bf16.f32 "
        "{%0,%1,%2,%3}, {%4,%5,%6,%7}, {%8,%9}, {%0,%1,%2,%3};"
        : "+f"(c[0]), "+f"(c[1]), "+f"(c[2]), "+f"(c[3])
        : "r"(a[0]), "r"(a[1]), "r"(a[2]), "r"(a[3]), "r"(b0), "r"(b1));
}

// ---------------------------------------------------------------------------
// bf16x3 GEMM via mma.sync:  C[128,128] tile of A[M,K] @ B[N,K]^T
//   A tensor = [2*aHalf, K] bf16 (hi rows then lo rows); same for B.
// EPI: 0 = sigmoid -> out   1 = out = W0 - lr*acc   2 = out + z*B*D = acc
// ---------------------------------------------------------------------------
template <int EPI>
__global__ __launch_bounds__(256, 1)
void gemm_mma(const __nv_bfloat16* __restrict__ Ahl, int lda, int aHalf,
              const __nv_bfloat16* __restrict__ Bhl, int ldb, int bHalf,
              int niter,
              const float* __restrict__ W0, const float* __restrict__ lr_p,
              float* __restrict__ out, int ldo)
{
    extern __shared__ char smem[];
    const uint32_t sb = smem_u32(smem);
    const int tid  = threadIdx.x;
    const int wid  = tid >> 5;
    const int lane = tid & 31;
    const int wm   = wid & 3;       // 4-way M split (32 rows each)
    const int wn   = wid >> 2;      // 2-way N split (64 cols each)
    const int m0   = blockIdx.y * CTA_M;
    const int n0   = blockIdx.x * CTA_N;
    const int k0g  = (EPI == 2) ? blockIdx.z * niter * CTA_K : 0;

    // cp.async staging map: 2048 16B chunks / stage, 8 per thread
    auto load_stage = [&](int stage, int it) {
        const uint32_t stg = sb + stage * STAGE_BYTES;
        const int kel = k0g + it * CTA_K;
#pragma unroll
        for (int i = 0; i < 8; i++) {
            const int c   = tid + i * 256;
            const int buf = c >> 9;
            const int cc  = c & 511;
            const int row = cc >> 2;
            const int seg = cc & 3;
            const __nv_bfloat16* src;
            if      (buf == 0) src = Ahl + (size_t)(m0 + row) * lda + kel + seg * 8;
            else if (buf == 1) src = Ahl + (size_t)(aHalf + m0 + row) * lda + kel + seg * 8;
            else if (buf == 2) src = Bhl + (size_t)(n0 + row) * ldb + kel + seg * 8;
            else               src = Bhl + (size_t)(bHalf + n0 + row) * ldb + kel + seg * 8;
            cp16(stg + buf * BUF_BYTES + row * ROW_PITCH + seg * 16, src);
        }
        cp_commit();
    };

    float acc[2][8][4];
#pragma unroll
    for (int i = 0; i < 2; i++)
#pragma unroll
        for (int j = 0; j < 8; j++)
#pragma unroll
            for (int v = 0; v < 4; v++) acc[i][j][v] = 0.0f;

    // ldmatrix lane decomposition
    const int rl = lane & 7;             // row within 8x8 tile
    const int hm = (lane >> 3) & 1;      // +8 row group
    const int kh = (lane >> 4) & 1;      // +8 k group (16B)

    // Prologue: stages 0, 1
    load_stage(0, 0);
    load_stage(1, 1);

    for (int it = 0; it < niter; it++) {
        if (it == niter - 1) cp_wait<0>(); else cp_wait<1>();
        __syncthreads();
        if (it + STAGES - 1 < niter)
            load_stage((it + STAGES - 1) % STAGES, it + STAGES - 1);

        const uint32_t stg = sb + (it % STAGES) * STAGE_BYTES;
#pragma unroll
        for (int ks = 0; ks < 2; ks++) {
            const int koff = ks * 32;    // 16 bf16 = 32 bytes
            uint32_t ah[2][4], al[2][4];
#pragma unroll
            for (int i = 0; i < 2; i++) {
                const int r = wm * 32 + i * 16 + hm * 8 + rl;
                const uint32_t a = stg + r * ROW_PITCH + koff + kh * 16;
                ldsm4(ah[i], a);
                ldsm4(al[i], a + BUF_BYTES);
            }
            uint32_t bh[4][4], bl[4][4];
#pragma unroll
            for (int q = 0; q < 4; q++) {
                const int r = wn * 64 + q * 16 + hm * 8 + rl;
                const uint32_t a = stg + 2 * BUF_BYTES + r * ROW_PITCH + koff + kh * 16;
                ldsm4(bh[q], a);
                ldsm4(bl[q], a + BUF_BYTES);
            }
            // PRODUCT-MAJOR ordering: 16 independent accs between reuses of the
            // same accumulator -> tensor pipe stays fully pipelined (no RAW chain).
#pragma unroll
            for (int i = 0; i < 2; i++)
#pragma unroll
                for (int q = 0; q < 4; q++)
#pragma unroll
                    for (int h = 0; h < 2; h++)
                        mma16816(acc[i][2 * q + h], ah[i], bh[q][h], bh[q][h + 2]);
#pragma unroll
            for (int i = 0; i < 2; i++)
#pragma unroll
                for (int q = 0; q < 4; q++)
#pragma unroll
                    for (int h = 0; h < 2; h++)
                        mma16816(acc[i][2 * q + h], ah[i], bl[q][h], bl[q][h + 2]);
#pragma unroll
            for (int i = 0; i < 2; i++)
#pragma unroll
                for (int q = 0; q < 4; q++)
#pragma unroll
                    for (int h = 0; h < 2; h++)
                        mma16816(acc[i][2 * q + h], al[i], bh[q][h], bh[q][h + 2]);
        }
        __syncthreads();
    }

    // Epilogue
    const int t4 = lane >> 2;
    const int t2 = (lane & 3) * 2;
    float lrv = 0.0f;
    if (EPI == 1) lrv = __ldg(lr_p);
    float* optr = out;
    if (EPI == 2) optr = out + (size_t)blockIdx.z * ((size_t)B_DIM * D_DIM);

#pragma unroll
    for (int i = 0; i < 2; i++) {
        const int row = m0 + wm * 32 + i * 16 + t4;
#pragma unroll
        for (int j = 0; j < 8; j++) {
            const int col = n0 + wn * 64 + j * 8 + t2;
            float v0 = acc[i][j][0], v1 = acc[i][j][1];
            float v2 = acc[i][j][2], v3 = acc[i][j][3];
            if (EPI == 0) {
                v0 = 1.0f / (1.0f + __expf(-v0));
                v1 = 1.0f / (1.0f + __expf(-v1));
                v2 = 1.0f / (1.0f + __expf(-v2));
                v3 = 1.0f / (1.0f + __expf(-v3));
            } else if (EPI == 1) {
                float2 wa = *reinterpret_cast<const float2*>(&W0[(size_t)row * ldo + col]);
                float2 wb = *reinterpret_cast<const float2*>(&W0[(size_t)(row + 8) * ldo + col]);
                v0 = wa.x - lrv * v0; v1 = wa.y - lrv * v1;
                v2 = wb.x - lrv * v2; v3 = wb.y - lrv * v3;
            }
            *reinterpret_cast<float2*>(&optr[(size_t)row * ldo + col]) = make_float2(v0, v1);
            *reinterpret_cast<float2*>(&optr[(size_t)(row + 8) * ldo + col]) = make_float2(v2, v3);
        }
    }
}

// ---------------------------------------------------------------------------
// Convert fp32 [R,C] -> hl [2R,C] bf16 (hi rows, lo rows) and hlT [2C,R] bf16.
// ---------------------------------------------------------------------------
__global__ __launch_bounds__(256)
void k_conv_pair(const float* __restrict__ src, __nv_bfloat16* __restrict__ hl,
                 __nv_bfloat16* __restrict__ hlT, int R, int C)
{
    __shared__ float t[32][65];
    const int bx = blockIdx.x * 64;   // cols
    const int by = blockIdx.y * 32;   // rows
    const int tx = threadIdx.x, ty = threadIdx.y;

#pragma unroll
    for (int dy = 0; dy < 4; dy++) {
        int row = ty + 8 * dy;
        float2 v = *reinterpret_cast<const float2*>(&src[(size_t)(by + row) * C + bx + 2 * tx]);
        t[row][2 * tx] = v.x; t[row][2 * tx + 1] = v.y;
    }
    __syncthreads();

#pragma unroll
    for (int dy = 0; dy < 4; dy++) {
        int row = ty + 8 * dy;
        float f0 = t[row][2 * tx], f1 = t[row][2 * tx + 1];
        __nv_bfloat16 h0 = __float2bfloat16(f0), h1 = __float2bfloat16(f1);
        __nv_bfloat16 l0 = __float2bfloat16(f0 - __bfloat162float(h0));
        __nv_bfloat16 l1 = __float2bfloat16(f1 - __bfloat162float(h1));
        __nv_bfloat162 hp; hp.x = h0; hp.y = h1;
        __nv_bfloat162 lp; lp.x = l0; lp.y = l1;
        *reinterpret_cast<__nv_bfloat162*>(&hl[(size_t)(by + row) * C + bx + 2 * tx]) = hp;
        *reinterpret_cast<__nv_bfloat162*>(&hl[((size_t)R + by + row) * C + bx + 2 * tx]) = lp;
    }
#pragma unroll
    for (int dc = 0; dc < 8; dc++) {
        int c = ty + 8 * dc;
        float f = t[tx][c];
        __nv_bfloat16 h = __float2bfloat16(f);
        __nv_bfloat16 l = __float2bfloat16(f - __bfloat162float(h));
        hlT[((size_t)bx + c) * R + by + tx] = h;
        hlT[((size_t)C + bx + c) * R + by + tx] = l;
    }
}

// ---------------------------------------------------------------------------
// Scatter: g[label_cols[i], label_rows[i]] -= 1 (const add: order-invariant)
// ---------------------------------------------------------------------------
__global__ void k_scatter(const int* __restrict__ rows, const int* __restrict__ cols) {
    int i = blockIdx.x * blockDim.x + threadIdx.x;
    if (i < NNZ_DIM)
        atomicAdd(&g_buf[(size_t)cols[i] * B_DIM + rows[i]], -1.0f);
}

// ---------------------------------------------------------------------------
// Deterministic fixed-order split-K reduction
// ---------------------------------------------------------------------------
__global__ __launch_bounds__(256)
void k4_reduce(float* __restrict__ grad) {
    const int n = B_DIM * D_DIM;
    int i4 = blockIdx.x * blockDim.x + threadIdx.x;
    if (i4 * 4 >= n) return;
    float4 s = make_float4(0.f, 0.f, 0.f, 0.f);
#pragma unroll
    for (int z = 0; z < K3_SPLITS; z++) {
        float4 v = *reinterpret_cast<const float4*>(&part_buf[(size_t)z * n + i4 * 4]);
        s.x += v.x; s.y += v.y; s.z += v.z; s.w += v.w;
    }
    *reinterpret_cast<float4*>(&grad[i4 * 4]) = s;
}

// ---------------------------------------------------------------------------
// Launch. Output layout: [grad_input (B*D) | w_new (L*D)]
// ---------------------------------------------------------------------------
extern "C" void kernel_launch(void* const* d_in, const int* in_sizes, int n_in,
                              void* d_out, int out_size) {
    const float* embed  = nullptr;
    const float* weight = nullptr;
    const float* lr     = nullptr;
    const int*   rows   = nullptr;
    const int*   cols   = nullptr;
    for (int i = 0; i < n_in; i++) {
        int s = in_sizes[i];
        if (s == B_DIM * D_DIM)                 embed  = (const float*)d_in[i];
        else if (s == 1)                        lr     = (const float*)d_in[i];
        else if (s == NNZ_DIM) {
            if (!rows) rows = (const int*)d_in[i];
            else       cols = (const int*)d_in[i];
        } else                                  weight = (const float*)d_in[i];
    }

    float* out  = (float*)d_out;
    float* grad = out;                                   // [B, D]
    float* wout = out + (size_t)B_DIM * D_DIM;           // [L, D]

    void *gp, *pWhl, *pWThl, *pghl, *pgThl, *pEhl, *pEThl, *pp;
    cudaGetSymbolAddress(&gp,    g_buf);
    cudaGetSymbolAddress(&pWhl,  Whl);
    cudaGetSymbolAddress(&pWThl, WThl);
    cudaGetSymbolAddress(&pghl,  ghl);
    cudaGetSymbolAddress(&pgThl, gThl);
    cudaGetSymbolAddress(&pEhl,  Ehl);
    cudaGetSymbolAddress(&pEThl, EThl);
    cudaGetSymbolAddress(&pp,    part_buf);

    cudaFuncSetAttribute(gemm_mma<0>, cudaFuncAttributeMaxDynamicSharedMemorySize, GEMM_SMEM);
    cudaFuncSetAttribute(gemm_mma<1>, cudaFuncAttributeMaxDynamicSharedMemorySize, GEMM_SMEM);
    cudaFuncSetAttribute(gemm_mma<2>, cudaFuncAttributeMaxDynamicSharedMemorySize, GEMM_SMEM);

    // Convert E and W to bf16 hi/lo (+ transposed copies)
    k_conv_pair<<<dim3(D_DIM / 64, B_DIM / 32), dim3(32, 8)>>>(
        embed, (__nv_bfloat16*)pEhl, (__nv_bfloat16*)pEThl, B_DIM, D_DIM);
    k_conv_pair<<<dim3(D_DIM / 64, L_DIM / 32), dim3(32, 8)>>>(
        weight, (__nv_bfloat16*)pWhl, (__nv_bfloat16*)pWThl, L_DIM, D_DIM);

    // K1: g = sigmoid(W @ E^T)  [L,B], K = 768 -> 24 iters
    gemm_mma<0><<<dim3(B_DIM / CTA_N, L_DIM / CTA_M, 1), 256, GEMM_SMEM>>>(
        (const __nv_bfloat16*)pWhl, D_DIM, L_DIM,
        (const __nv_bfloat16*)pEhl, D_DIM, B_DIM,
        D_DIM / CTA_K, nullptr, nullptr, (float*)gp, B_DIM);

    // scatter -1 at positives
    k_scatter<<<NNZ_DIM / 256, 256>>>(rows, cols);

    // Convert g to bf16 hi/lo (+ transposed)
    k_conv_pair<<<dim3(B_DIM / 64, L_DIM / 32), dim3(32, 8)>>>(
        (const float*)gp, (__nv_bfloat16*)pghl, (__nv_bfloat16*)pgThl, L_DIM, B_DIM);

    // K2: Wout = W - lr*(g @ E)  [L,D], K = 512 -> 16 iters
    gemm_mma<1><<<dim3(D_DIM / CTA_N, L_DIM / CTA_M, 1), 256, GEMM_SMEM>>>(
        (const __nv_bfloat16*)pghl, B_DIM, L_DIM,
        (const __nv_bfloat16*)pEThl, B_DIM, D_DIM,
        B_DIM / CTA_K, weight, lr, wout, D_DIM);

    // K3: part[z] = (g^T @ W) chunk  [B,D], K-chunk = 4096 -> 128 iters, 32 slices
    gemm_mma<2><<<dim3(D_DIM / CTA_N, B_DIM / CTA_M, K3_SPLITS), 256, GEMM_SMEM>>>(
        (const __nv_bfloat16*)pgThl, L_DIM, B_DIM,
        (const __nv_bfloat16*)pWThl, L_DIM, D_DIM,
        K3_CHUNK / CTA_K, nullptr, nullptr, (float*)pp, D_DIM);

    // Deterministic fixed-order reduce
    k4_reduce<<<(B_DIM * D_DIM / 4 + 255) / 256, 256>>>(grad);
}

// round 11
// speedup vs baseline: 1.0257x; 1.0257x over previous
#include <cuda_runtime.h>
#include <cuda_bf16.h>
#include <cstdint>

// Problem dims (fixed by the dataset)
#define L_DIM 131072
#define B_DIM 512
#define D_DIM 768
#define NNZ_DIM 2048

#define K3_SPLITS 32
#define K3_CHUNK (L_DIM / K3_SPLITS)   // 4096

// GEMM tiling (mma.sync path, plain sm_100-compatible)
#define CTA_M 128
#define CTA_N 128
#define CTA_K 32
#define STAGES 4
#define ROW_PITCH 80                     // 64B data + 16B pad -> conflict-free LDSM
#define BUF_BYTES (128 * ROW_PITCH)      // 10240 per operand-half
#define STAGE_BYTES (4 * BUF_BYTES)      // Ahi, Alo, Bhi, Blo = 40960
#define GEMM_SMEM (STAGES * STAGE_BYTES) // 163840

// ---------------------------------------------------------------------------
// Scratch (__device__ globals = allocation-free scratch)
// ---------------------------------------------------------------------------
static __device__ float          g_buf[(size_t)L_DIM * B_DIM];                 // fp32 g
static __device__ __nv_bfloat16  Whl [(size_t)2 * L_DIM * D_DIM];              // [2L, D]
static __device__ __nv_bfloat16  WThl[(size_t)2 * D_DIM * L_DIM];              // [2D, L]
static __device__ __nv_bfloat16  ghl [(size_t)2 * L_DIM * B_DIM];              // [2L, B]
static __device__ __nv_bfloat16  gThl[(size_t)2 * B_DIM * L_DIM];              // [2B, L]
static __device__ __nv_bfloat16  Ehl [(size_t)2 * B_DIM * D_DIM];              // [2B, D]
static __device__ __nv_bfloat16  EThl[(size_t)2 * D_DIM * B_DIM];              // [2D, B]
static __device__ float          part_buf[(size_t)K3_SPLITS * B_DIM * D_DIM];

// ---------------------------------------------------------------------------
// sm_80-level PTX helpers (legal on plain sm_100 target)
// ---------------------------------------------------------------------------
__device__ __forceinline__ uint32_t smem_u32(const void* p) {
    uint32_t a;
    asm("{ .reg .u64 t; cvta.to.shared.u64 t, %1; cvt.u32.u64 %0, t; }" : "=r"(a) : "l"(p));
    return a;
}
__device__ __forceinline__ void cp16(uint32_t dst, const void* src) {
    asm volatile("cp.async.cg.shared.global [%0], [%1], 16;" :: "r"(dst), "l"(src));
}
__device__ __forceinline__ void cp_commit() {
    asm volatile("cp.async.commit_group;" ::: "memory");
}
template <int N>
__device__ __forceinline__ void cp_wait() {
    asm volatile("cp.async.wait_group %0;" :: "n"(N) : "memory");
}
__device__ __forceinline__ void ldsm4(uint32_t* d, uint32_t addr) {
    asm volatile("ldmatrix.sync.aligned.m8n8.x4.shared.b16 {%0,%1,%2,%3}, [%4];"
        : "=r"(d[0]), "=r"(d[1]), "=r"(d[2]), "=r"(d[3]) : "r"(addr));
}
__device__ __forceinline__ void mma16816(float* c, const uint32_t* a, uint32_t b0, uint32_t b1) {
    asm volatile("mma.sync.aligned.m16n8k16.row.col.f32.bf16.bf16.f32 "
        "{%0,%1,%2,%3}, {%4,%5,%6,%7}, {%8,%9}, {%0,%1,%2,%3};"
        : "+f"(c[0]), "+f"(c[1]), "+f"(c[2]), "+f"(c[3])
        : "r"(a[0]), "r"(a[1]), "r"(a[2]), "r"(a[3]), "r"(b0), "r"(b1));
}

// ---------------------------------------------------------------------------
// bf16x3 GEMM via mma.sync:  C[128,128] tile of A[M,K] @ B[N,K]^T
//   A tensor = [2*aHalf, K] bf16 (hi rows then lo rows); same for B.
// EPI: 0 = sigmoid -> out   1 = out = W0 - lr*acc   2 = out + z*B*D = acc
// ---------------------------------------------------------------------------
template <int EPI>
__global__ __launch_bounds__(256, 1)
void gemm_mma(const __nv_bfloat16* __restrict__ Ahl, int lda, int aHalf,
              const __nv_bfloat16* __restrict__ Bhl, int ldb, int bHalf,
              int niter,
              const float* __restrict__ W0, const float* __restrict__ lr_p,
              float* __restrict__ out, int ldo)
{
    extern __shared__ char smem[];
    const uint32_t sb = smem_u32(smem);
    const int tid  = threadIdx.x;
    const int wid  = tid >> 5;
    const int lane = tid & 31;
    const int wm   = wid & 3;       // 4-way M split (32 rows each)
    const int wn   = wid >> 2;      // 2-way N split (64 cols each)
    const int m0   = blockIdx.y * CTA_M;
    const int n0   = blockIdx.x * CTA_N;
    const int k0g  = (EPI == 2) ? blockIdx.z * niter * CTA_K : 0;

    // cp.async staging map: 2048 16B chunks / stage, 8 per thread
    auto load_stage = [&](int stage, int it) {
        const uint32_t stg = sb + stage * STAGE_BYTES;
        const int kel = k0g + it * CTA_K;
#pragma unroll
        for (int i = 0; i < 8; i++) {
            const int c   = tid + i * 256;
            const int buf = c >> 9;
            const int cc  = c & 511;
            const int row = cc >> 2;
            const int seg = cc & 3;
            const __nv_bfloat16* src;
            if      (buf == 0) src = Ahl + (size_t)(m0 + row) * lda + kel + seg * 8;
            else if (buf == 1) src = Ahl + (size_t)(aHalf + m0 + row) * lda + kel + seg * 8;
            else if (buf == 2) src = Bhl + (size_t)(n0 + row) * ldb + kel + seg * 8;
            else               src = Bhl + (size_t)(bHalf + n0 + row) * ldb + kel + seg * 8;
            cp16(stg + buf * BUF_BYTES + row * ROW_PITCH + seg * 16, src);
        }
        cp_commit();
    };

    float acc[2][8][4];
#pragma unroll
    for (int i = 0; i < 2; i++)
#pragma unroll
        for (int j = 0; j < 8; j++)
#pragma unroll
            for (int v = 0; v < 4; v++) acc[i][j][v] = 0.0f;

    // ldmatrix lane decomposition
    const int rl = lane & 7;             // row within 8x8 tile
    const int hm = (lane >> 3) & 1;      // +8 row group
    const int kh = (lane >> 4) & 1;      // +8 k group (16B)

    // Prologue: stages 0..STAGES-2
    load_stage(0, 0);
    load_stage(1, 1);
    load_stage(2, 2);

    for (int it = 0; it < niter; it++) {
        // Ensure group for stage `it` has landed (tail-aware selection)
        if      (it < niter - 2) cp_wait<2>();
        else if (it == niter - 2) cp_wait<1>();
        else                      cp_wait<0>();
        __syncthreads();   // also protects buffer (it+STAGES-1)%STAGES, last read at it-1
        if (it + STAGES - 1 < niter)
            load_stage((it + STAGES - 1) % STAGES, it + STAGES - 1);

        const uint32_t stg = sb + (it % STAGES) * STAGE_BYTES;
#pragma unroll
        for (int ks = 0; ks < 2; ks++) {
            const int koff = ks * 32;    // 16 bf16 = 32 bytes
            uint32_t ah[2][4], al[2][4];
#pragma unroll
            for (int i = 0; i < 2; i++) {
                const int r = wm * 32 + i * 16 + hm * 8 + rl;
                const uint32_t a = stg + r * ROW_PITCH + koff + kh * 16;
                ldsm4(ah[i], a);
                ldsm4(al[i], a + BUF_BYTES);
            }
            uint32_t bh[4][4], bl[4][4];
#pragma unroll
            for (int q = 0; q < 4; q++) {
                const int r = wn * 64 + q * 16 + hm * 8 + rl;
                const uint32_t a = stg + 2 * BUF_BYTES + r * ROW_PITCH + koff + kh * 16;
                ldsm4(bh[q], a);
                ldsm4(bl[q], a + BUF_BYTES);
            }
            // PRODUCT-MAJOR ordering: 16 independent accumulators between
            // reuses of the same acc quad -> no tensor RAW chain.
#pragma unroll
            for (int i = 0; i < 2; i++)
#pragma unroll
                for (int q = 0; q < 4; q++)
#pragma unroll
                    for (int h = 0; h < 2; h++)
                        mma16816(acc[i][2 * q + h], ah[i], bh[q][h], bh[q][h + 2]);
#pragma unroll
            for (int i = 0; i < 2; i++)
#pragma unroll
                for (int q = 0; q < 4; q++)
#pragma unroll
                    for (int h = 0; h < 2; h++)
                        mma16816(acc[i][2 * q + h], ah[i], bl[q][h], bl[q][h + 2]);
#pragma unroll
            for (int i = 0; i < 2; i++)
#pragma unroll
                for (int q = 0; q < 4; q++)
#pragma unroll
                    for (int h = 0; h < 2; h++)
                        mma16816(acc[i][2 * q + h], al[i], bh[q][h], bh[q][h + 2]);
        }
        // NOTE: no trailing __syncthreads -- the top-of-loop barrier at it+1
        // already orders reads of stage it%STAGES against future overwrites.
    }

    // Epilogue
    const int t4 = lane >> 2;
    const int t2 = (lane & 3) * 2;
    float lrv = 0.0f;
    if (EPI == 1) lrv = __ldg(lr_p);
    float* optr = out;
    if (EPI == 2) optr = out + (size_t)blockIdx.z * ((size_t)B_DIM * D_DIM);

#pragma unroll
    for (int i = 0; i < 2; i++) {
        const int row = m0 + wm * 32 + i * 16 + t4;
#pragma unroll
        for (int j = 0; j < 8; j++) {
            const int col = n0 + wn * 64 + j * 8 + t2;
            float v0 = acc[i][j][0], v1 = acc[i][j][1];
            float v2 = acc[i][j][2], v3 = acc[i][j][3];
            if (EPI == 0) {
                v0 = 1.0f / (1.0f + __expf(-v0));
                v1 = 1.0f / (1.0f + __expf(-v1));
                v2 = 1.0f / (1.0f + __expf(-v2));
                v3 = 1.0f / (1.0f + __expf(-v3));
            } else if (EPI == 1) {
                float2 wa = *reinterpret_cast<const float2*>(&W0[(size_t)row * ldo + col]);
                float2 wb = *reinterpret_cast<const float2*>(&W0[(size_t)(row + 8) * ldo + col]);
                v0 = wa.x - lrv * v0; v1 = wa.y - lrv * v1;
                v2 = wb.x - lrv * v2; v3 = wb.y - lrv * v3;
            }
            *reinterpret_cast<float2*>(&optr[(size_t)row * ldo + col]) = make_float2(v0, v1);
            *reinterpret_cast<float2*>(&optr[(size_t)(row + 8) * ldo + col]) = make_float2(v2, v3);
        }
    }
}

// ---------------------------------------------------------------------------
// Convert fp32 [R,C] -> hl [2R,C] bf16 (hi rows, lo rows) and hlT [2C,R] bf16.
// by0 = row-tile offset (lets the host split one conversion into two launches).
// ---------------------------------------------------------------------------
__global__ __launch_bounds__(256)
void k_conv_pair(const float* __restrict__ src, __nv_bfloat16* __restrict__ hl,
                 __nv_bfloat16* __restrict__ hlT, int R, int C, int by0)
{
    __shared__ float t[32][65];
    const int bx = blockIdx.x * 64;               // cols
    const int by = (blockIdx.y + by0) * 32;       // rows
    const int tx = threadIdx.x, ty = threadIdx.y;

#pragma unroll
    for (int dy = 0; dy < 4; dy++) {
        int row = ty + 8 * dy;
        float2 v = *reinterpret_cast<const float2*>(&src[(size_t)(by + row) * C + bx + 2 * tx]);
        t[row][2 * tx] = v.x; t[row][2 * tx + 1] = v.y;
    }
    __syncthreads();

#pragma unroll
    for (int dy = 0; dy < 4; dy++) {
        int row = ty + 8 * dy;
        float f0 = t[row][2 * tx], f1 = t[row][2 * tx + 1];
        __nv_bfloat16 h0 = __float2bfloat16(f0), h1 = __float2bfloat16(f1);
        __nv_bfloat16 l0 = __float2bfloat16(f0 - __bfloat162float(h0));
        __nv_bfloat16 l1 = __float2bfloat16(f1 - __bfloat162float(h1));
        __nv_bfloat162 hp; hp.x = h0; hp.y = h1;
        __nv_bfloat162 lp; lp.x = l0; lp.y = l1;
        *reinterpret_cast<__nv_bfloat162*>(&hl[(size_t)(by + row) * C + bx + 2 * tx]) = hp;
        *reinterpret_cast<__nv_bfloat162*>(&hl[((size_t)R + by + row) * C + bx + 2 * tx]) = lp;
    }
#pragma unroll
    for (int dc = 0; dc < 8; dc++) {
        int c = ty + 8 * dc;
        float f = t[tx][c];
        __nv_bfloat16 h = __float2bfloat16(f);
        __nv_bfloat16 l = __float2bfloat16(f - __bfloat162float(h));
        hlT[((size_t)bx + c) * R + by + tx] = h;
        hlT[((size_t)C + bx + c) * R + by + tx] = l;
    }
}

// ---------------------------------------------------------------------------
// Scatter: g[label_cols[i], label_rows[i]] -= 1 (const add: order-invariant)
// ---------------------------------------------------------------------------
__global__ void k_scatter(const int* __restrict__ rows, const int* __restrict__ cols) {
    int i = blockIdx.x * blockDim.x + threadIdx.x;
    if (i < NNZ_DIM)
        atomicAdd(&g_buf[(size_t)cols[i] * B_DIM + rows[i]], -1.0f);
}

// ---------------------------------------------------------------------------
// Deterministic fixed-order split-K reduction
// ---------------------------------------------------------------------------
__global__ __launch_bounds__(256)
void k4_reduce(float* __restrict__ grad) {
    const int n = B_DIM * D_DIM;
    int i4 = blockIdx.x * blockDim.x + threadIdx.x;
    if (i4 * 4 >= n) return;
    float4 s = make_float4(0.f, 0.f, 0.f, 0.f);
#pragma unroll
    for (int z = 0; z < K3_SPLITS; z++) {
        float4 v = *reinterpret_cast<const float4*>(&part_buf[(size_t)z * n + i4 * 4]);
        s.x += v.x; s.y += v.y; s.z += v.z; s.w += v.w;
    }
    *reinterpret_cast<float4*>(&grad[i4 * 4]) = s;
}

// ---------------------------------------------------------------------------
// Launch. Output layout: [grad_input (B*D) | w_new (L*D)]
// Launch order puts K1 (GEMM) in slot 4 = the slot ncu has been capturing.
// ---------------------------------------------------------------------------
extern "C" void kernel_launch(void* const* d_in, const int* in_sizes, int n_in,
                              void* d_out, int out_size) {
    const float* embed  = nullptr;
    const float* weight = nullptr;
    const float* lr     = nullptr;
    const int*   rows   = nullptr;
    const int*   cols   = nullptr;
    for (int i = 0; i < n_in; i++) {
        int s = in_sizes[i];
        if (s == B_DIM * D_DIM)                 embed  = (const float*)d_in[i];
        else if (s == 1)                        lr     = (const float*)d_in[i];
        else if (s == NNZ_DIM) {
            if (!rows) rows = (const int*)d_in[i];
            else       cols = (const int*)d_in[i];
        } else                                  weight = (const float*)d_in[i];
    }

    float* out  = (float*)d_out;
    float* grad = out;                                   // [B, D]
    float* wout = out + (size_t)B_DIM * D_DIM;           // [L, D]

    void *gp, *pWhl, *pWThl, *pghl, *pgThl, *pEhl, *pEThl, *pp;
    cudaGetSymbolAddress(&gp,    g_buf);
    cudaGetSymbolAddress(&pWhl,  Whl);
    cudaGetSymbolAddress(&pWThl, WThl);
    cudaGetSymbolAddress(&pghl,  ghl);
    cudaGetSymbolAddress(&pgThl, gThl);
    cudaGetSymbolAddress(&pEhl,  Ehl);
    cudaGetSymbolAddress(&pEThl, EThl);
    cudaGetSymbolAddress(&pp,    part_buf);

    cudaFuncSetAttribute(gemm_mma<0>, cudaFuncAttributeMaxDynamicSharedMemorySize, GEMM_SMEM);
    cudaFuncSetAttribute(gemm_mma<1>, cudaFuncAttributeMaxDynamicSharedMemorySize, GEMM_SMEM);
    cudaFuncSetAttribute(gemm_mma<2>, cudaFuncAttributeMaxDynamicSharedMemorySize, GEMM_SMEM);

    const int LH = L_DIM / 2;
    // 1,2) Convert W (split into two launches so K1 lands in ncu's capture slot)
    k_conv_pair<<<dim3(D_DIM / 64, LH / 32), dim3(32, 8)>>>(
        weight, (__nv_bfloat16*)pWhl, (__nv_bfloat16*)pWThl, L_DIM, D_DIM, 0);
    k_conv_pair<<<dim3(D_DIM / 64, LH / 32), dim3(32, 8)>>>(
        weight, (__nv_bfloat16*)pWhl, (__nv_bfloat16*)pWThl, L_DIM, D_DIM, LH / 32);
    // 3) Convert E
    k_conv_pair<<<dim3(D_DIM / 64, B_DIM / 32), dim3(32, 8)>>>(
        embed, (__nv_bfloat16*)pEhl, (__nv_bfloat16*)pEThl, B_DIM, D_DIM, 0);

    // 4) K1: g = sigmoid(W @ E^T)  [L,B], K = 768 -> 24 iters
    gemm_mma<0><<<dim3(B_DIM / CTA_N, L_DIM / CTA_M, 1), 256, GEMM_SMEM>>>(
        (const __nv_bfloat16*)pWhl, D_DIM, L_DIM,
        (const __nv_bfloat16*)pEhl, D_DIM, B_DIM,
        D_DIM / CTA_K, nullptr, nullptr, (float*)gp, B_DIM);

    // 5) scatter -1 at positives
    k_scatter<<<NNZ_DIM / 256, 256>>>(rows, cols);

    // 6) Convert g to bf16 hi/lo (+ transposed)
    k_conv_pair<<<dim3(B_DIM / 64, L_DIM / 32), dim3(32, 8)>>>(
        (const float*)gp, (__nv_bfloat16*)pghl, (__nv_bfloat16*)pgThl, L_DIM, B_DIM, 0);

    // 7) K2: Wout = W - lr*(g @ E)  [L,D], K = 512 -> 16 iters
    gemm_mma<1><<<dim3(D_DIM / CTA_N, L_DIM / CTA_M, 1), 256, GEMM_SMEM>>>(
        (const __nv_bfloat16*)pghl, B_DIM, L_DIM,
        (const __nv_bfloat16*)pEThl, B_DIM, D_DIM,
        B_DIM / CTA_K, weight, lr, wout, D_DIM);

    // 8) K3: part[z] = (g^T @ W) chunk  [B,D], K-chunk = 4096 -> 128 iters
    gemm_mma<2><<<dim3(D_DIM / CTA_N, B_DIM / CTA_M, K3_SPLITS), 256, GEMM_SMEM>>>(
        (const __nv_bfloat16*)pgThl, L_DIM, B_DIM,
        (const __nv_bfloat16*)pWThl, L_DIM, D_DIM,
        K3_CHUNK / CTA_K, nullptr, nullptr, (float*)pp, D_DIM);

    // 9) Deterministic fixed-order reduce
    k4_reduce<<<(B_DIM * D_DIM / 4 + 255) / 256, 256>>>(grad);
}

// round 13
// speedup vs baseline: 1.1608x; 1.1317x over previous
#include <cuda_runtime.h>
#include <cuda_bf16.h>
#include <cstdint>

// Problem dims (fixed by the dataset)
#define L_DIM 131072
#define B_DIM 512
#define D_DIM 768
#define NNZ_DIM 2048

#define K3_SPLITS 32
#define K3_CHUNK (L_DIM / K3_SPLITS)   // 4096

// GEMM tiling (mma.sync path, plain sm_100-compatible)
#define CTA_M 128
#define CTA_N 128
#define CTA_K 32
#define STAGES 2
#define ROW_PITCH 80                     // 64B data + 16B pad -> conflict-free LDSM
#define BUF_BYTES (128 * ROW_PITCH)      // 10240 per operand-half
#define STAGE_BYTES (4 * BUF_BYTES)      // Ahi, Alo, Bhi, Blo = 40960
#define GEMM_SMEM (STAGES * STAGE_BYTES) // 81920 -> 2 CTAs/SM (160KB < 227KB)

// ---------------------------------------------------------------------------
// Scratch (__device__ globals = allocation-free scratch)
// ---------------------------------------------------------------------------
static __device__ float          g_buf[(size_t)L_DIM * B_DIM];                 // fp32 g
static __device__ __nv_bfloat16  Whl [(size_t)2 * L_DIM * D_DIM];              // [2L, D]
static __device__ __nv_bfloat16  WThl[(size_t)2 * D_DIM * L_DIM];              // [2D, L]
static __device__ __nv_bfloat16  ghl [(size_t)2 * L_DIM * B_DIM];              // [2L, B]
static __device__ __nv_bfloat16  gThl[(size_t)2 * B_DIM * L_DIM];              // [2B, L]
static __device__ __nv_bfloat16  Ehl [(size_t)2 * B_DIM * D_DIM];              // [2B, D]
static __device__ __nv_bfloat16  EThl[(size_t)2 * D_DIM * B_DIM];              // [2D, B]
static __device__ float          part_buf[(size_t)K3_SPLITS * B_DIM * D_DIM];

// ---------------------------------------------------------------------------
// sm_80-level PTX helpers (legal on plain sm_100 target)
// ---------------------------------------------------------------------------
__device__ __forceinline__ uint32_t smem_u32(const void* p) {
    uint32_t a;
    asm("{ .reg .u64 t; cvta.to.shared.u64 t, %1; cvt.u32.u64 %0, t; }" : "=r"(a) : "l"(p));
    return a;
}
__device__ __forceinline__ void cp16(uint32_t dst, const void* src) {
    asm volatile("cp.async.cg.shared.global [%0], [%1], 16;" :: "r"(dst), "l"(src));
}
__device__ __forceinline__ void cp_commit() {
    asm volatile("cp.async.commit_group;" ::: "memory");
}
template <int N>
__device__ __forceinline__ void cp_wait() {
    asm volatile("cp.async.wait_group %0;" :: "n"(N) : "memory");
}
__device__ __forceinline__ void ldsm4(uint32_t* d, uint32_t addr) {
    asm volatile("ldmatrix.sync.aligned.m8n8.x4.shared.b16 {%0,%1,%2,%3}, [%4];"
        : "=r"(d[0]), "=r"(d[1]), "=r"(d[2]), "=r"(d[3]) : "r"(addr));
}
__device__ __forceinline__ void mma16816(float* c, const uint32_t* a, uint32_t b0, uint32_t b1) {
    asm volatile("mma.sync.aligned.m16n8k16.row.col.f32.bf16.bf16.f32 "
        "{%0,%1,%2,%3}, {%4,%5,%6,%7}, {%8,%9}, {%0,%1,%2,%3};"
        : "+f"(c[0]), "+f"(c[1]), "+f"(c[2]), "+f"(c[3])
        : "r"(a[0]), "r"(a[1]), "r"(a[2]), "r"(a[3]), "r"(b0), "r"(b1));
}

// ---------------------------------------------------------------------------
// bf16x3 GEMM via mma.sync:  C[128,128] tile of A[M,K] @ B[N,K]^T
//   A tensor = [2*aHalf, K] bf16 (hi rows then lo rows); same for B.
// EPI: 0 = sigmoid -> out   1 = out = W0 - lr*acc   2 = out + z*B*D = acc
// 2 CTAs/SM (16 warps) to feed the tensor pipe; 2-stage cp.async pipeline.
// ---------------------------------------------------------------------------
template <int EPI>
__global__ __launch_bounds__(256, 2)
void gemm_mma(const __nv_bfloat16* __restrict__ Ahl, int lda, int aHalf,
              const __nv_bfloat16* __restrict__ Bhl, int ldb, int bHalf,
              int niter,
              const float* __restrict__ W0, const float* __restrict__ lr_p,
              float* __restrict__ out, int ldo)
{
    extern __shared__ char smem[];
    const uint32_t sb = smem_u32(smem);
    const int tid  = threadIdx.x;
    const int wid  = tid >> 5;
    const int lane = tid & 31;
    const int wm   = wid & 3;       // 4-way M split (32 rows each)
    const int wn   = wid >> 2;      // 2-way N split (64 cols each)
    const int m0   = blockIdx.y * CTA_M;
    const int n0   = blockIdx.x * CTA_N;
    const int k0g  = (EPI == 2) ? blockIdx.z * niter * CTA_K : 0;

    // cp.async staging map: 2048 16B chunks / stage, 8 per thread
    auto load_stage = [&](int stage, int it) {
        const uint32_t stg = sb + stage * STAGE_BYTES;
        const int kel = k0g + it * CTA_K;
#pragma unroll
        for (int i = 0; i < 8; i++) {
            const int c   = tid + i * 256;
            const int buf = c >> 9;
            const int cc  = c & 511;
            const int row = cc >> 2;
            const int seg = cc & 3;
            const __nv_bfloat16* src;
            if      (buf == 0) src = Ahl + (size_t)(m0 + row) * lda + kel + seg * 8;
            else if (buf == 1) src = Ahl + (size_t)(aHalf + m0 + row) * lda + kel + seg * 8;
            else if (buf == 2) src = Bhl + (size_t)(n0 + row) * ldb + kel + seg * 8;
            else               src = Bhl + (size_t)(bHalf + n0 + row) * ldb + kel + seg * 8;
            cp16(stg + buf * BUF_BYTES + row * ROW_PITCH + seg * 16, src);
        }
        cp_commit();
    };

    float acc[2][8][4];
#pragma unroll
    for (int i = 0; i < 2; i++)
#pragma unroll
        for (int j = 0; j < 8; j++)
#pragma unroll
            for (int v = 0; v < 4; v++) acc[i][j][v] = 0.0f;

    // ldmatrix lane decomposition
    const int rl = lane & 7;             // row within 8x8 tile
    const int hm = (lane >> 3) & 1;      // +8 row group
    const int kh = (lane >> 4) & 1;      // +8 k group (16B)

    // Prologue: stage 0 <- iter 0
    load_stage(0, 0);

    for (int it = 0; it < niter; it++) {
        cp_wait<0>();        // group for iter `it` landed (committed at it-1 / prologue)
        __syncthreads();     // also: stage (it+1)%2 last read at it-1 -> safe to overwrite
        if (it + 1 < niter)
            load_stage((it + 1) % STAGES, it + 1);

        const uint32_t stg = sb + (it % STAGES) * STAGE_BYTES;
#pragma unroll
        for (int ks = 0; ks < 2; ks++) {
            const int koff = ks * 32;    // 16 bf16 = 32 bytes
            uint32_t ah[2][4], al[2][4];
#pragma unroll
            for (int i = 0; i < 2; i++) {
                const int r = wm * 32 + i * 16 + hm * 8 + rl;
                const uint32_t a = stg + r * ROW_PITCH + koff + kh * 16;
                ldsm4(ah[i], a);
                ldsm4(al[i], a + BUF_BYTES);
            }
            uint32_t bh[4][4], bl[4][4];
#pragma unroll
            for (int q = 0; q < 4; q++) {
                const int r = wn * 64 + q * 16 + hm * 8 + rl;
                const uint32_t a = stg + 2 * BUF_BYTES + r * ROW_PITCH + koff + kh * 16;
                ldsm4(bh[q], a);
                ldsm4(bl[q], a + BUF_BYTES);
            }
            // PRODUCT-MAJOR ordering: 16 independent accumulators between
            // reuses of the same acc quad -> no tensor RAW chain.
#pragma unroll
            for (int i = 0; i < 2; i++)
#pragma unroll
                for (int q = 0; q < 4; q++)
#pragma unroll
                    for (int h = 0; h < 2; h++)
                        mma16816(acc[i][2 * q + h], ah[i], bh[q][h], bh[q][h + 2]);
#pragma unroll
            for (int i = 0; i < 2; i++)
#pragma unroll
                for (int q = 0; q < 4; q++)
#pragma unroll
                    for (int h = 0; h < 2; h++)
                        mma16816(acc[i][2 * q + h], ah[i], bl[q][h], bl[q][h + 2]);
#pragma unroll
            for (int i = 0; i < 2; i++)
#pragma unroll
                for (int q = 0; q < 4; q++)
#pragma unroll
                    for (int h = 0; h < 2; h++)
                        mma16816(acc[i][2 * q + h], al[i], bh[q][h], bh[q][h + 2]);
        }
    }

    // Epilogue
    const int t4 = lane >> 2;
    const int t2 = (lane & 3) * 2;
    float lrv = 0.0f;
    if (EPI == 1) lrv = __ldg(lr_p);
    float* optr = out;
    if (EPI == 2) optr = out + (size_t)blockIdx.z * ((size_t)B_DIM * D_DIM);

#pragma unroll
    for (int i = 0; i < 2; i++) {
        const int row = m0 + wm * 32 + i * 16 + t4;
#pragma unroll
        for (int j = 0; j < 8; j++) {
            const int col = n0 + wn * 64 + j * 8 + t2;
            float v0 = acc[i][j][0], v1 = acc[i][j][1];
            float v2 = acc[i][j][2], v3 = acc[i][j][3];
            if (EPI == 0) {
                v0 = 1.0f / (1.0f + __expf(-v0));
                v1 = 1.0f / (1.0f + __expf(-v1));
                v2 = 1.0f / (1.0f + __expf(-v2));
                v3 = 1.0f / (1.0f + __expf(-v3));
            } else if (EPI == 1) {
                float2 wa = *reinterpret_cast<const float2*>(&W0[(size_t)row * ldo + col]);
                float2 wb = *reinterpret_cast<const float2*>(&W0[(size_t)(row + 8) * ldo + col]);
                v0 = wa.x - lrv * v0; v1 = wa.y - lrv * v1;
                v2 = wb.x - lrv * v2; v3 = wb.y - lrv * v3;
            }
            *reinterpret_cast<float2*>(&optr[(size_t)row * ldo + col]) = make_float2(v0, v1);
            *reinterpret_cast<float2*>(&optr[(size_t)(row + 8) * ldo + col]) = make_float2(v2, v3);
        }
    }
}

// ---------------------------------------------------------------------------
// Convert fp32 [R,C] -> hl [2R,C] bf16 (hi rows, lo rows) and hlT [2C,R] bf16.
// by0 = row-tile offset (lets the host split one conversion into two launches).
// ---------------------------------------------------------------------------
__global__ __launch_bounds__(256)
void k_conv_pair(const float* __restrict__ src, __nv_bfloat16* __restrict__ hl,
                 __nv_bfloat16* __restrict__ hlT, int R, int C, int by0)
{
    __shared__ float t[32][65];
    const int bx = blockIdx.x * 64;               // cols
    const int by = (blockIdx.y + by0) * 32;       // rows
    const int tx = threadIdx.x, ty = threadIdx.y;

#pragma unroll
    for (int dy = 0; dy < 4; dy++) {
        int row = ty + 8 * dy;
        float2 v = *reinterpret_cast<const float2*>(&src[(size_t)(by + row) * C + bx + 2 * tx]);
        t[row][2 * tx] = v.x; t[row][2 * tx + 1] = v.y;
    }
    __syncthreads();

#pragma unroll
    for (int dy = 0; dy < 4; dy++) {
        int row = ty + 8 * dy;
        float f0 = t[row][2 * tx], f1 = t[row][2 * tx + 1];
        __nv_bfloat16 h0 = __float2bfloat16(f0), h1 = __float2bfloat16(f1);
        __nv_bfloat16 l0 = __float2bfloat16(f0 - __bfloat162float(h0));
        __nv_bfloat16 l1 = __float2bfloat16(f1 - __bfloat162float(h1));
        __nv_bfloat162 hp; hp.x = h0; hp.y = h1;
        __nv_bfloat162 lp; lp.x = l0; lp.y = l1;
        *reinterpret_cast<__nv_bfloat162*>(&hl[(size_t)(by + row) * C + bx + 2 * tx]) = hp;
        *reinterpret_cast<__nv_bfloat162*>(&hl[((size_t)R + by + row) * C + bx + 2 * tx]) = lp;
    }
#pragma unroll
    for (int dc = 0; dc < 8; dc++) {
        int c = ty + 8 * dc;
        float f = t[tx][c];
        __nv_bfloat16 h = __float2bfloat16(f);
        __nv_bfloat16 l = __float2bfloat16(f - __bfloat162float(h));
        hlT[((size_t)bx + c) * R + by + tx] = h;
        hlT[((size_t)C + bx + c) * R + by + tx] = l;
    }
}

// ---------------------------------------------------------------------------
// Scatter: g[label_cols[i], label_rows[i]] -= 1 (const add: order-invariant)
// ---------------------------------------------------------------------------
__global__ void k_scatter(const int* __restrict__ rows, const int* __restrict__ cols) {
    int i = blockIdx.x * blockDim.x + threadIdx.x;
    if (i < NNZ_DIM)
        atomicAdd(&g_buf[(size_t)cols[i] * B_DIM + rows[i]], -1.0f);
}

// ---------------------------------------------------------------------------
// Deterministic fixed-order split-K reduction
// ---------------------------------------------------------------------------
__global__ __launch_bounds__(256)
void k4_reduce(float* __restrict__ grad) {
    const int n = B_DIM * D_DIM;
    int i4 = blockIdx.x * blockDim.x + threadIdx.x;
    if (i4 * 4 >= n) return;
    float4 s = make_float4(0.f, 0.f, 0.f, 0.f);
#pragma unroll
    for (int z = 0; z < K3_SPLITS; z++) {
        float4 v = *reinterpret_cast<const float4*>(&part_buf[(size_t)z * n + i4 * 4]);
        s.x += v.x; s.y += v.y; s.z += v.z; s.w += v.w;
    }
    *reinterpret_cast<float4*>(&grad[i4 * 4]) = s;
}

// ---------------------------------------------------------------------------
// Launch. Output layout: [grad_input (B*D) | w_new (L*D)]
// Launch order keeps K1 (GEMM) in slot 4 = ncu's capture slot.
// ---------------------------------------------------------------------------
extern "C" void kernel_launch(void* const* d_in, const int* in_sizes, int n_in,
                              void* d_out, int out_size) {
    const float* embed  = nullptr;
    const float* weight = nullptr;
    const float* lr     = nullptr;
    const int*   rows   = nullptr;
    const int*   cols   = nullptr;
    for (int i = 0; i < n_in; i++) {
        int s = in_sizes[i];
        if (s == B_DIM * D_DIM)                 embed  = (const float*)d_in[i];
        else if (s == 1)                        lr     = (const float*)d_in[i];
        else if (s == NNZ_DIM) {
            if (!rows) rows = (const int*)d_in[i];
            else       cols = (const int*)d_in[i];
        } else                                  weight = (const float*)d_in[i];
    }

    float* out  = (float*)d_out;
    float* grad = out;                                   // [B, D]
    float* wout = out + (size_t)B_DIM * D_DIM;           // [L, D]

    void *gp, *pWhl, *pWThl, *pghl, *pgThl, *pEhl, *pEThl, *pp;
    cudaGetSymbolAddress(&gp,    g_buf);
    cudaGetSymbolAddress(&pWhl,  Whl);
    cudaGetSymbolAddress(&pWThl, WThl);
    cudaGetSymbolAddress(&pghl,  ghl);
    cudaGetSymbolAddress(&pgThl, gThl);
    cudaGetSymbolAddress(&pEhl,  Ehl);
    cudaGetSymbolAddress(&pEThl, EThl);
    cudaGetSymbolAddress(&pp,    part_buf);

    cudaFuncSetAttribute(gemm_mma<0>, cudaFuncAttributeMaxDynamicSharedMemorySize, GEMM_SMEM);
    cudaFuncSetAttribute(gemm_mma<1>, cudaFuncAttributeMaxDynamicSharedMemorySize, GEMM_SMEM);
    cudaFuncSetAttribute(gemm_mma<2>, cudaFuncAttributeMaxDynamicSharedMemorySize, GEMM_SMEM);

    const int LH = L_DIM / 2;
    // 1,2) Convert W (split into two launches so K1 lands in ncu's capture slot)
    k_conv_pair<<<dim3(D_DIM / 64, LH / 32), dim3(32, 8)>>>(
        weight, (__nv_bfloat16*)pWhl, (__nv_bfloat16*)pWThl, L_DIM, D_DIM, 0);
    k_conv_pair<<<dim3(D_DIM / 64, LH / 32), dim3(32, 8)>>>(
        weight, (__nv_bfloat16*)pWhl, (__nv_bfloat16*)pWThl, L_DIM, D_DIM, LH / 32);
    // 3) Convert E
    k_conv_pair<<<dim3(D_DIM / 64, B_DIM / 32), dim3(32, 8)>>>(
        embed, (__nv_bfloat16*)pEhl, (__nv_bfloat16*)pEThl, B_DIM, D_DIM, 0);

    // 4) K1: g = sigmoid(W @ E^T)  [L,B], K = 768 -> 24 iters
    gemm_mma<0><<<dim3(B_DIM / CTA_N, L_DIM / CTA_M, 1), 256, GEMM_SMEM>>>(
        (const __nv_bfloat16*)pWhl, D_DIM, L_DIM,
        (const __nv_bfloat16*)pEhl, D_DIM, B_DIM,
        D_DIM / CTA_K, nullptr, nullptr, (float*)gp, B_DIM);

    // 5) scatter -1 at positives
    k_scatter<<<NNZ_DIM / 256, 256>>>(rows, cols);

    // 6) Convert g to bf16 hi/lo (+ transposed)
    k_conv_pair<<<dim3(B_DIM / 64, L_DIM / 32), dim3(32, 8)>>>(
        (const float*)gp, (__nv_bfloat16*)pghl, (__nv_bfloat16*)pgThl, L_DIM, B_DIM, 0);

    // 7) K2: Wout = W - lr*(g @ E)  [L,D], K = 512 -> 16 iters
    gemm_mma<1><<<dim3(D_DIM / CTA_N, L_DIM / CTA_M, 1), 256, GEMM_SMEM>>>(
        (const __nv_bfloat16*)pghl, B_DIM, L_DIM,
        (const __nv_bfloat16*)pEThl, B_DIM, D_DIM,
        B_DIM / CTA_K, weight, lr, wout, D_DIM);

    // 8) K3: part[z] = (g^T @ W) chunk  [B,D], K-chunk = 4096 -> 128 iters
    gemm_mma<2><<<dim3(D_DIM / CTA_N, B_DIM / CTA_M, K3_SPLITS), 256, GEMM_SMEM>>>(
        (const __nv_bfloat16*)pgThl, L_DIM, B_DIM,
        (const __nv_bfloat16*)pWThl, L_DIM, D_DIM,
        K3_CHUNK / CTA_K, nullptr, nullptr, (float*)pp, D_DIM);

    // 9) Deterministic fixed-order reduce
    k4_reduce<<<(B_DIM * D_DIM / 4 + 255) / 256, 256>>>(grad);
}